// round 16
// baseline (speedup 1.0000x reference)
#include <cuda_runtime.h>
#include <cuda_bf16.h>
#include <math.h>
#include <stdint.h>

#define Bb 16
#define Tt 1024
#define Ss 2048
#define Hh 1024
#define MT 16384          // B*T
#define HB 8              // half batch

// ---------------- global scratch (allocation-free rule) ---------------------
__device__ __nv_bfloat16 g_out_hi[(long)MT * Hh],  g_out_lo[(long)MT * Hh];
__device__ __nv_bfloat16 g_w_hi[(long)Hh * Hh],    g_w_lo[(long)Hh * Hh];
__device__ __nv_bfloat16 g_w2_hi[(long)Hh * 2 * Hh], g_w2_lo[(long)Hh * 2 * Hh];
__device__ __nv_bfloat16 g_ctx_hi[(long)Bb * Ss * Hh], g_ctx_lo[(long)Bb * Ss * Hh];
__device__ __nv_bfloat16 g_ctxT_hi[(long)Bb * Hh * Ss], g_ctxT_lo[(long)Bb * Hh * Ss];
__device__ __nv_bfloat16 g_q_hi[(long)MT * Hh],    g_q_lo[(long)MT * Hh];
__device__ __nv_bfloat16 g_attn_hi[(long)MT * Ss], g_attn_lo[(long)MT * Ss];
__device__ __nv_bfloat16 g_mix_hi[(long)MT * Hh],  g_mix_lo[(long)MT * Hh];

// ---------------- PTX helpers (all sm_80+ arch-agnostic) --------------------
__device__ __forceinline__ uint32_t smem_u32(const void* p) {
    uint32_t a;
    asm("{ .reg .u64 t; cvta.to.shared.u64 t, %1; cvt.u32.u64 %0, t; }" : "=r"(a) : "l"(p));
    return a;
}
#define CP_ASYNC16(dst, src) \
    asm volatile("cp.async.cg.shared.global [%0], [%1], 16;" :: "r"(dst), "l"(src) : "memory")
#define CP_COMMIT() asm volatile("cp.async.commit_group;" ::: "memory")
#define CP_WAIT1()  asm volatile("cp.async.wait_group 1;" ::: "memory")

#define LDM4(r, a) \
    asm volatile("ldmatrix.sync.aligned.m8n8.x4.shared.b16 {%0,%1,%2,%3}, [%4];" \
        : "=r"((r)[0]), "=r"((r)[1]), "=r"((r)[2]), "=r"((r)[3]) : "r"(a))

#define MMA_BF16(d, a, b0, b1) \
    asm volatile("mma.sync.aligned.m16n8k16.row.col.f32.bf16.bf16.f32 " \
        "{%0,%1,%2,%3}, {%4,%5,%6,%7}, {%8,%9}, {%0,%1,%2,%3};" \
        : "+f"((d)[0]), "+f"((d)[1]), "+f"((d)[2]), "+f"((d)[3]) \
        : "r"((a)[0]), "r"((a)[1]), "r"((a)[2]), "r"((a)[3]), "r"(b0), "r"(b1))

// Tile: CTA 128(M) x 128(N), 4 warps (2m x 2n), warp tile 64x64, KC=32.
// 2 CTAs/SM; 16B-granule XOR swizzle part^=(row&3).
#define ROWB   64
#define AMATB  8192
#define BMATB  8192
#define STG    32768
#define NSTG   3
#define SMEM_TOTAL (NSTG * STG)   // 98304 per CTA (x2 CTAs = 192K)
#define KC     32

// ---------------------------------------------------------------------------
// HMMA bf16 GEMM with 2-term hi/lo split: C[M,N] = A[M,K] * B[N,K]^T
// EPI: 0 = fp32 store, 1 = bf16 hi/lo split store, 2 = tanh(x+bias) fp32
// ---------------------------------------------------------------------------
template <int EPI>
__global__ __launch_bounds__(128, 2)
void hmma_gemm(const __nv_bfloat16* __restrict__ Ah, const __nv_bfloat16* __restrict__ Al,
               const __nv_bfloat16* __restrict__ A2h, const __nv_bfloat16* __restrict__ A2l,
               int kSplit, int lda, int lda2, long aBatch,
               const __nv_bfloat16* __restrict__ Bh, const __nv_bfloat16* __restrict__ Bl,
               int ldb, long bBatch, int K,
               float* __restrict__ C, long cBatch, int ldc,
               __nv_bfloat16* __restrict__ Chi, __nv_bfloat16* __restrict__ Clo,
               const float* __restrict__ bias)
{
    extern __shared__ char smem[];
    const uint32_t sb = smem_u32(smem);
    const int tid = threadIdx.x;
    const int l   = tid & 31;
    const int wid = tid >> 5;      // 0..3
    const int wm  = wid >> 1;      // 0..1
    const int wn  = wid & 1;       // 0..1

    const int m0 = blockIdx.y * 128;
    const int n0 = blockIdx.x * 128;
    const int z  = blockIdx.z;
    Ah  += (long)z * aBatch;  Al  += (long)z * aBatch;
    A2h += (long)z * aBatch;  A2l += (long)z * aBatch;
    Bh  += (long)z * bBatch;  Bl  += (long)z * bBatch;

    const int nchunks = K / KC;
    const int ksChunk = kSplit / KC;   // chunk index where A switches to A2

    // ---- incremental per-thread loader state ----
    // Each thread owns rows {rowbase + 32*j} (j=0..3) of each matrix, 16B at
    // column slot 'part'. Swizzled dst offset is chunk-invariant.
    const int rowbase = tid >> 2;          // 0..31
    const int part    = tid & 3;           // 0..3
    const uint32_t swz = (uint32_t)((part ^ (rowbase & 3)) << 4);
    const uint32_t dstA = (uint32_t)rowbase * ROWB + swz;              // + j*2048
    const long laStep = (long)lda * 32;    // A row-group stride (elements)
    const long lbStep = (long)ldb * 32;

    const __nv_bfloat16* sAh = Ah + (long)(m0 + rowbase) * lda + part * 8;
    const __nv_bfloat16* sAl = Al + (long)(m0 + rowbase) * lda + part * 8;
    const __nv_bfloat16* sBh = Bh + (long)(n0 + rowbase) * ldb + part * 8;
    const __nv_bfloat16* sBl = Bl + (long)(n0 + rowbase) * ldb + part * 8;
    long laStepCur = laStep;

    // issue chunk c into stage s; called once per c in increasing order
    auto issue = [&](int c, int s) {
        if (c >= nchunks) return;
        if (c == ksChunk) {   // switch A source (GEMM4 concat)
            sAh = A2h + (long)(m0 + rowbase) * lda2 + part * 8;
            sAl = A2l + (long)(m0 + rowbase) * lda2 + part * 8;
            laStepCur = (long)lda2 * 32;
        }
        const uint32_t st = sb + s * STG + dstA;
#pragma unroll
        for (int j = 0; j < 4; j++) {
            CP_ASYNC16(st + j * 2048,              sAh + j * laStepCur);
            CP_ASYNC16(st + AMATB + j * 2048,      sAl + j * laStepCur);
            CP_ASYNC16(st + 2 * AMATB + j * 2048,  sBh + j * lbStep);
            CP_ASYNC16(st + 3 * AMATB + j * 2048,  sBl + j * lbStep);
        }
        sAh += KC; sAl += KC; sBh += KC; sBl += KC;
    };

    float acc[4][8][4];
#pragma unroll
    for (int mf = 0; mf < 4; mf++)
#pragma unroll
        for (int nf = 0; nf < 8; nf++)
#pragma unroll
            for (int r = 0; r < 4; r++) acc[mf][nf][r] = 0.f;

    issue(0, 0); CP_COMMIT();
    issue(1, 1); CP_COMMIT();

    const int rowA   = l & 15;
    const int partA0 = l >> 4;
    const int rowBl  = ((l >> 4) << 3) + (l & 7);
    const int partB0 = (l >> 3) & 1;

    for (int c = 0; c < nchunks; c++) {
        // R13-proven ordering: per-warp wait FIRST, then barrier.
        // The barrier after the wait is what makes OTHER warps' cp.async
        // writes for chunk c visible (wait_group is per-warp only), and it
        // simultaneously protects the stage that issue() overwrites next.
        CP_WAIT1();                      // my groups: chunk c landed
        __syncthreads();                 // all warps landed + done reading (c+2)%3's old data
        issue(c + 2, (c + 2) % NSTG);    // refill stage consumed at chunk c-1
        CP_COMMIT();

        const uint32_t base = sb + (c % NSTG) * STG;
#pragma unroll
        for (int ks = 0; ks < 2; ks++) {
            uint32_t a_hi[4][4], a_lo[4][4];
#pragma unroll
            for (int mf = 0; mf < 4; mf++) {
                const int row  = wm * 64 + mf * 16 + rowA;
                const int prt  = ks * 2 + partA0;
                uint32_t off = base + (uint32_t)row * ROWB +
                               (uint32_t)((prt ^ (row & 3)) << 4);
                LDM4(a_hi[mf], off);
                LDM4(a_lo[mf], off + AMATB);
            }
            uint32_t b_hi[4][4], b_lo[4][4];
#pragma unroll
            for (int nf2 = 0; nf2 < 4; nf2++) {
                const int row  = wn * 64 + nf2 * 16 + rowBl;
                const int prt  = ks * 2 + partB0;
                uint32_t off = base + 2 * AMATB + (uint32_t)row * ROWB +
                               (uint32_t)((prt ^ (row & 3)) << 4);
                LDM4(b_hi[nf2], off);
                LDM4(b_lo[nf2], off + BMATB);
            }
#pragma unroll
            for (int mf = 0; mf < 4; mf++)
#pragma unroll
                for (int nf2 = 0; nf2 < 4; nf2++)
#pragma unroll
                    for (int h = 0; h < 2; h++) {
                        const int nf = nf2 * 2 + h;
                        MMA_BF16(acc[mf][nf], a_hi[mf], b_hi[nf2][h * 2], b_hi[nf2][h * 2 + 1]);
                        MMA_BF16(acc[mf][nf], a_hi[mf], b_lo[nf2][h * 2], b_lo[nf2][h * 2 + 1]);
                        MMA_BF16(acc[mf][nf], a_lo[mf], b_hi[nf2][h * 2], b_hi[nf2][h * 2 + 1]);
                    }
        }
    }

    float* Cb = C + (long)z * cBatch;
    __nv_bfloat16* Chb = Chi + (long)z * cBatch;
    __nv_bfloat16* Clb = Clo + (long)z * cBatch;
#pragma unroll
    for (int mf = 0; mf < 4; mf++)
#pragma unroll
        for (int nf = 0; nf < 8; nf++)
#pragma unroll
            for (int h2 = 0; h2 < 2; h2++) {
                const int m = m0 + wm * 64 + mf * 16 + h2 * 8 + (l >> 2);
                const int n = n0 + wn * 64 + nf * 8 + (l & 3) * 2;
                float v0 = acc[mf][nf][h2 * 2 + 0];
                float v1 = acc[mf][nf][h2 * 2 + 1];
                if (EPI == 0) {
                    float2 t = make_float2(v0, v1);
                    *(float2*)&Cb[(long)m * ldc + n] = t;
                } else if (EPI == 2) {
                    float2 t;
                    t.x = tanhf(v0 + bias[n]);
                    t.y = tanhf(v1 + bias[n + 1]);
                    *(float2*)&Cb[(long)m * ldc + n] = t;
                } else {
                    __nv_bfloat16 h0 = __float2bfloat16(v0);
                    __nv_bfloat16 h1 = __float2bfloat16(v1);
                    __nv_bfloat16 l0 = __float2bfloat16(v0 - __bfloat162float(h0));
                    __nv_bfloat16 l1 = __float2bfloat16(v1 - __bfloat162float(h1));
                    __nv_bfloat162 hp; hp.x = h0; hp.y = h1;
                    __nv_bfloat162 lp; lp.x = l0; lp.y = l1;
                    *(__nv_bfloat162*)&Chb[(long)m * ldc + n] = hp;
                    *(__nv_bfloat162*)&Clb[(long)m * ldc + n] = lp;
                }
            }
}

// ---------------------------------------------------------------------------
__global__ __launch_bounds__(256)
void cvt_hilo(const float* __restrict__ x, __nv_bfloat16* __restrict__ hi,
              __nv_bfloat16* __restrict__ lo, long n8)
{
    long i = (long)blockIdx.x * blockDim.x + threadIdx.x;
    if (i >= n8) return;
#pragma unroll
    for (int half = 0; half < 2; half++) {
        long e = i * 2 + half;
        float4 v = ((const float4*)x)[e];
        float f[4] = {v.x, v.y, v.z, v.w};
        __nv_bfloat16 h[4], l[4];
#pragma unroll
        for (int j = 0; j < 4; j++) {
            h[j] = __float2bfloat16(f[j]);
            l[j] = __float2bfloat16(f[j] - __bfloat162float(h[j]));
        }
        *(uint2*)&hi[e * 4] = *(uint2*)h;
        *(uint2*)&lo[e * 4] = *(uint2*)l;
    }
}

// ---------------------------------------------------------------------------
__global__ __launch_bounds__(256)
void transpose_cvt(const float* __restrict__ ctx,
                   __nv_bfloat16* __restrict__ chi, __nv_bfloat16* __restrict__ clo,
                   __nv_bfloat16* __restrict__ thi, __nv_bfloat16* __restrict__ tlo)
{
    __shared__ float tile[32][33];
    const int h0 = blockIdx.x * 32;
    const int s0 = blockIdx.y * 32;
    const int z  = blockIdx.z;
    const int tx = threadIdx.x & 31;
    const int ty = threadIdx.x >> 5;
    const long ibase = (long)z * Ss * Hh;
    const long obase = (long)z * Hh * Ss;
#pragma unroll
    for (int i = 0; i < 4; i++) {
        int s = s0 + ty + i * 8;
        float v = ctx[ibase + (long)s * Hh + h0 + tx];
        tile[ty + i * 8][tx] = v;
        __nv_bfloat16 hb = __float2bfloat16(v);
        __nv_bfloat16 lb = __float2bfloat16(v - __bfloat162float(hb));
        long o = ibase + (long)s * Hh + h0 + tx;
        chi[o] = hb;
        clo[o] = lb;
    }
    __syncthreads();
#pragma unroll
    for (int i = 0; i < 4; i++) {
        int h = h0 + ty + i * 8;
        float v = tile[tx][ty + i * 8];
        __nv_bfloat16 hb = __float2bfloat16(v);
        __nv_bfloat16 lb = __float2bfloat16(v - __bfloat162float(hb));
        long o = obase + (long)h * Ss + s0 + tx;
        thi[o] = hb;
        tlo[o] = lb;
    }
}

// ---------------------------------------------------------------------------
// In-place row softmax over S=2048 (vectorized), emits bf16 hi/lo too.
// ---------------------------------------------------------------------------
__global__ __launch_bounds__(256)
void softmax_kernel(float* __restrict__ attn, __nv_bfloat16* __restrict__ ahi,
                    __nv_bfloat16* __restrict__ alo)
{
    __shared__ float red[256];
    const long row = blockIdx.x;
    float* p = attn + row * (long)Ss;
    const int tid = threadIdx.x;
    const int e0 = tid * 8;

    float v[8];
    *(float4*)&v[0] = *(float4*)&p[e0];
    *(float4*)&v[4] = *(float4*)&p[e0 + 4];
    float mx = v[0];
#pragma unroll
    for (int i = 1; i < 8; i++) mx = fmaxf(mx, v[i]);
    red[tid] = mx;
    __syncthreads();
    for (int s = 128; s > 0; s >>= 1) {
        if (tid < s) red[tid] = fmaxf(red[tid], red[tid + s]);
        __syncthreads();
    }
    mx = red[0];
    __syncthreads();

    float sum = 0.f;
#pragma unroll
    for (int i = 0; i < 8; i++) {
        v[i] = __expf(v[i] - mx);
        sum += v[i];
    }
    red[tid] = sum;
    __syncthreads();
    for (int s = 128; s > 0; s >>= 1) {
        if (tid < s) red[tid] += red[tid + s];
        __syncthreads();
    }
    const float inv = 1.f / red[0];

    __nv_bfloat16 hb[8], lb[8];
#pragma unroll
    for (int i = 0; i < 8; i++) {
        v[i] *= inv;
        hb[i] = __float2bfloat16(v[i]);
        lb[i] = __float2bfloat16(v[i] - __bfloat162float(hb[i]));
    }
    *(float4*)&p[e0]     = *(float4*)&v[0];
    *(float4*)&p[e0 + 4] = *(float4*)&v[4];
    long o = row * (long)Ss + e0;
    *(uint2*)&ahi[o]     = *(uint2*)&hb[0];
    *(uint2*)&ahi[o + 4] = *(uint2*)&hb[4];
    *(uint2*)&alo[o]     = *(uint2*)&lb[0];
    *(uint2*)&alo[o + 4] = *(uint2*)&lb[4];
}

// ---------------------------------------------------------------------------
extern "C" void kernel_launch(void* const* d_in, const int* in_sizes, int n_in,
                              void* d_out, int out_size)
{
    const float* output  = (const float*)d_in[0];
    const float* context = (const float*)d_in[1];
    const float* attn_w  = (const float*)d_in[2];
    const float* w2      = (const float*)d_in[3];
    const float* b2      = (const float*)d_in[4];

    float* out  = (float*)d_out;                   // [B,T,H]
    float* attn = out + (long)MT * Hh;             // [B,T,S]

    void *outhi, *outlo, *whi, *wlo, *w2hi, *w2lo, *ctxhi, *ctxlo;
    void *ctxthi, *ctxtlo, *qhi, *qlo, *athi, *atlo, *mixhi, *mixlo;
    cudaGetSymbolAddress(&outhi, g_out_hi);   cudaGetSymbolAddress(&outlo, g_out_lo);
    cudaGetSymbolAddress(&whi, g_w_hi);       cudaGetSymbolAddress(&wlo, g_w_lo);
    cudaGetSymbolAddress(&w2hi, g_w2_hi);     cudaGetSymbolAddress(&w2lo, g_w2_lo);
    cudaGetSymbolAddress(&ctxhi, g_ctx_hi);   cudaGetSymbolAddress(&ctxlo, g_ctx_lo);
    cudaGetSymbolAddress(&ctxthi, g_ctxT_hi); cudaGetSymbolAddress(&ctxtlo, g_ctxT_lo);
    cudaGetSymbolAddress(&qhi, g_q_hi);       cudaGetSymbolAddress(&qlo, g_q_lo);
    cudaGetSymbolAddress(&athi, g_attn_hi);   cudaGetSymbolAddress(&atlo, g_attn_lo);
    cudaGetSymbolAddress(&mixhi, g_mix_hi);   cudaGetSymbolAddress(&mixlo, g_mix_lo);

    cudaFuncSetAttribute(hmma_gemm<0>, cudaFuncAttributeMaxDynamicSharedMemorySize, SMEM_TOTAL);
    cudaFuncSetAttribute(hmma_gemm<1>, cudaFuncAttributeMaxDynamicSharedMemorySize, SMEM_TOTAL);
    cudaFuncSetAttribute(hmma_gemm<2>, cudaFuncAttributeMaxDynamicSharedMemorySize, SMEM_TOTAL);

    const __nv_bfloat16* OH = (const __nv_bfloat16*)outhi;
    const __nv_bfloat16* OL = (const __nv_bfloat16*)outlo;
    const __nv_bfloat16* WH = (const __nv_bfloat16*)whi;
    const __nv_bfloat16* WL = (const __nv_bfloat16*)wlo;
    const __nv_bfloat16* W2H = (const __nv_bfloat16*)w2hi;
    const __nv_bfloat16* W2L = (const __nv_bfloat16*)w2lo;
    const __nv_bfloat16* CH = (const __nv_bfloat16*)ctxhi;
    const __nv_bfloat16* CL = (const __nv_bfloat16*)ctxlo;
    const __nv_bfloat16* CTH = (const __nv_bfloat16*)ctxthi;
    const __nv_bfloat16* CTL = (const __nv_bfloat16*)ctxtlo;
    const __nv_bfloat16* QH = (const __nv_bfloat16*)qhi;
    const __nv_bfloat16* QL = (const __nv_bfloat16*)qlo;
    const __nv_bfloat16* AH = (const __nv_bfloat16*)athi;
    const __nv_bfloat16* AL = (const __nv_bfloat16*)atlo;
    const __nv_bfloat16* MH = (const __nv_bfloat16*)mixhi;
    const __nv_bfloat16* ML = (const __nv_bfloat16*)mixlo;

    // fork-join resources (host-side only; no device memory)
    cudaStream_t side;
    cudaStreamCreateWithFlags(&side, cudaStreamNonBlocking);
    cudaEvent_t ev0, ev1, evA, evB;
    cudaEventCreateWithFlags(&ev0, cudaEventDisableTiming);
    cudaEventCreateWithFlags(&ev1, cudaEventDisableTiming);
    cudaEventCreateWithFlags(&evA, cudaEventDisableTiming);
    cudaEventCreateWithFlags(&evB, cudaEventDisableTiming);

    // ---- fork: side does ctx transpose+convert and w2 convert ----
    cudaEventRecord(ev0, 0);
    cudaStreamWaitEvent(side, ev0, 0);
    {
        dim3 g(Hh / 32, Ss / 32, Bb);
        transpose_cvt<<<g, 256, 0, side>>>(context, (__nv_bfloat16*)ctxhi, (__nv_bfloat16*)ctxlo,
                                           (__nv_bfloat16*)ctxthi, (__nv_bfloat16*)ctxtlo);
    }
    cvt_hilo<<<((long)Hh * 2 * Hh / 8 + 255) / 256, 256, 0, side>>>(
        w2, (__nv_bfloat16*)w2hi, (__nv_bfloat16*)w2lo, (long)Hh * 2 * Hh / 8);
    cudaEventRecord(ev1, side);

    // ---- main: out/w converts + GEMM1 ----
    cvt_hilo<<<(MT * (long)Hh / 8 + 255) / 256, 256>>>(output, (__nv_bfloat16*)outhi, (__nv_bfloat16*)outlo, MT * (long)Hh / 8);
    cvt_hilo<<<((long)Hh * Hh / 8 + 255) / 256, 256>>>(attn_w, (__nv_bfloat16*)whi, (__nv_bfloat16*)wlo, (long)Hh * Hh / 8);
    {
        dim3 grid(Hh / 128, MT / 128, 1);
        hmma_gemm<1><<<grid, 128, SMEM_TOTAL>>>(OH, OL, OH, OL, 1 << 30, Hh, Hh, 0L,
                                                WH, WL, Hh, 0L, Hh,
                                                nullptr, (long)MT * Hh, Hh,
                                                (__nv_bfloat16*)qhi, (__nv_bfloat16*)qlo, nullptr);
    }
    cudaStreamWaitEvent(0, ev1, 0);   // join: ctx ready

    // ---- GEMM2 in two batch halves ----
    const long aB2 = (long)Tt * Hh, bB2 = (long)Ss * Hh, cB2 = (long)Tt * Ss;
    {
        dim3 grid(Ss / 128, Tt / 128, HB);
        hmma_gemm<0><<<grid, 128, SMEM_TOTAL>>>(QH, QL, QH, QL, 1 << 30, Hh, Hh, aB2,
                                                CH, CL, Hh, bB2, Hh,
                                                attn, cB2, Ss, nullptr, nullptr, nullptr);
    }
    cudaEventRecord(evA, 0);
    {
        dim3 grid(Ss / 128, Tt / 128, HB);
        hmma_gemm<0><<<grid, 128, SMEM_TOTAL>>>(QH + HB * aB2, QL + HB * aB2,
                                                QH + HB * aB2, QL + HB * aB2, 1 << 30, Hh, Hh, aB2,
                                                CH + HB * bB2, CL + HB * bB2, Hh, bB2, Hh,
                                                attn + HB * cB2, cB2, Ss, nullptr, nullptr, nullptr);
    }

    // ---- side: softmax h1 + GEMM3 h1 ----
    const long aB3 = (long)Tt * Ss, bB3 = (long)Hh * Ss, cB3 = (long)Tt * Hh;
    cudaStreamWaitEvent(side, evA, 0);
    softmax_kernel<<<MT / 2, 256, 0, side>>>(attn, (__nv_bfloat16*)athi, (__nv_bfloat16*)atlo);
    {
        dim3 grid(Hh / 128, Tt / 128, HB);
        hmma_gemm<1><<<grid, 128, SMEM_TOTAL, side>>>(AH, AL, AH, AL, 1 << 30, Ss, Ss, aB3,
                                                      CTH, CTL, Ss, bB3, Ss,
                                                      nullptr, cB3, Hh,
                                                      (__nv_bfloat16*)mixhi, (__nv_bfloat16*)mixlo, nullptr);
    }
    cudaEventRecord(evB, side);

    // ---- main: softmax h2 + GEMM3 h2 ----
    softmax_kernel<<<MT / 2, 256>>>(attn + HB * cB2,
                                    (__nv_bfloat16*)athi + HB * cB2,
                                    (__nv_bfloat16*)atlo + HB * cB2);
    {
        dim3 grid(Hh / 128, Tt / 128, HB);
        hmma_gemm<1><<<grid, 128, SMEM_TOTAL>>>(AH + HB * aB3, AL + HB * aB3,
                                                AH + HB * aB3, AL + HB * aB3, 1 << 30, Ss, Ss, aB3,
                                                CTH + HB * bB3, CTL + HB * bB3, Ss, bB3, Ss,
                                                nullptr, cB3, Hh,
                                                (__nv_bfloat16*)mixhi + HB * cB3,
                                                (__nv_bfloat16*)mixlo + HB * cB3, nullptr);
    }
    cudaStreamWaitEvent(0, evB, 0);   // join: mix h1 ready

    // ---- GEMM4 ----
    {
        dim3 grid(Hh / 128, MT / 128, 1);
        hmma_gemm<2><<<grid, 128, SMEM_TOTAL>>>(MH, ML, QH, QL, Hh, Hh, Hh, 0L,
                                                W2H, W2L, 2 * Hh, 0L, 2 * Hh,
                                                out, (long)MT * Hh, Hh,
                                                nullptr, nullptr, b2);
    }
    // note: streams/events intentionally not destroyed while referenced by capture
}

// round 17
// speedup vs baseline: 1.4740x; 1.4740x over previous
#include <cuda_runtime.h>
#include <cuda_bf16.h>
#include <math.h>
#include <stdint.h>

#define Bb 16
#define Tt 1024
#define Ss 2048
#define Hh 1024
#define MT 16384          // B*T
#define HB 8              // half batch

// ---------------- global scratch (allocation-free rule) ---------------------
__device__ __nv_bfloat16 g_out_hi[(long)MT * Hh],  g_out_lo[(long)MT * Hh];
__device__ __nv_bfloat16 g_w_hi[(long)Hh * Hh],    g_w_lo[(long)Hh * Hh];
__device__ __nv_bfloat16 g_w2_hi[(long)Hh * 2 * Hh], g_w2_lo[(long)Hh * 2 * Hh];
__device__ __nv_bfloat16 g_ctx_hi[(long)Bb * Ss * Hh], g_ctx_lo[(long)Bb * Ss * Hh];
__device__ __nv_bfloat16 g_ctxT_hi[(long)Bb * Hh * Ss], g_ctxT_lo[(long)Bb * Hh * Ss];
__device__ __nv_bfloat16 g_q_hi[(long)MT * Hh],    g_q_lo[(long)MT * Hh];
__device__ __nv_bfloat16 g_attn_hi[(long)MT * Ss], g_attn_lo[(long)MT * Ss];
__device__ __nv_bfloat16 g_mix_hi[(long)MT * Hh],  g_mix_lo[(long)MT * Hh];

// ---------------- PTX helpers (all sm_80+ arch-agnostic) --------------------
__device__ __forceinline__ uint32_t smem_u32(const void* p) {
    uint32_t a;
    asm("{ .reg .u64 t; cvta.to.shared.u64 t, %1; cvt.u32.u64 %0, t; }" : "=r"(a) : "l"(p));
    return a;
}
#define CP_ASYNC16(dst, src) \
    asm volatile("cp.async.cg.shared.global [%0], [%1], 16;" :: "r"(dst), "l"(src) : "memory")
#define CP_COMMIT() asm volatile("cp.async.commit_group;" ::: "memory")
#define CP_WAIT1()  asm volatile("cp.async.wait_group 1;" ::: "memory")

#define LDM4(r, a) \
    asm volatile("ldmatrix.sync.aligned.m8n8.x4.shared.b16 {%0,%1,%2,%3}, [%4];" \
        : "=r"((r)[0]), "=r"((r)[1]), "=r"((r)[2]), "=r"((r)[3]) : "r"(a))

#define MMA_BF16(d, a, b0, b1) \
    asm volatile("mma.sync.aligned.m16n8k16.row.col.f32.bf16.bf16.f32 " \
        "{%0,%1,%2,%3}, {%4,%5,%6,%7}, {%8,%9}, {%0,%1,%2,%3};" \
        : "+f"((d)[0]), "+f"((d)[1]), "+f"((d)[2]), "+f"((d)[3]) \
        : "r"((a)[0]), "r"((a)[1]), "r"((a)[2]), "r"((a)[3]), "r"(b0), "r"(b1))

// Tile: CTA 128(M) x 128(N), 4 warps (2m x 2n), warp tile 64x64, KC=32.
// 2 CTAs/SM; 16B-granule XOR swizzle part^=(row&3).
#define ROWB   64
#define AMATB  8192
#define BMATB  8192
#define STG    32768
#define NSTG   3
#define SMEM_TOTAL (NSTG * STG)   // 98304 per CTA (x2 CTAs = 192K)
#define KC     32

// ---------------------------------------------------------------------------
// HMMA bf16 GEMM with 2-term hi/lo split: C[M,N] = A[M,K] * B[N,K]^T
// EPI: 0 = fp32 store, 1 = bf16 hi/lo split store, 2 = tanh(x+bias) fp32
// Loader recomputes addresses from loop-invariant components each chunk
// (R13-proven; persistent pointer state regressed via spills in R16).
// ---------------------------------------------------------------------------
template <int EPI>
__global__ __launch_bounds__(128, 2)
void hmma_gemm(const __nv_bfloat16* __restrict__ Ah, const __nv_bfloat16* __restrict__ Al,
               const __nv_bfloat16* __restrict__ A2h, const __nv_bfloat16* __restrict__ A2l,
               int kSplit, int lda, int lda2, long aBatch,
               const __nv_bfloat16* __restrict__ Bh, const __nv_bfloat16* __restrict__ Bl,
               int ldb, long bBatch, int K,
               float* __restrict__ C, long cBatch, int ldc,
               __nv_bfloat16* __restrict__ Chi, __nv_bfloat16* __restrict__ Clo,
               const float* __restrict__ bias)
{
    extern __shared__ char smem[];
    const uint32_t sb = smem_u32(smem);
    const int tid = threadIdx.x;
    const int l   = tid & 31;
    const int wid = tid >> 5;      // 0..3
    const int wm  = wid >> 1;      // 0..1
    const int wn  = wid & 1;       // 0..1

    const int m0 = blockIdx.y * 128;
    const int n0 = blockIdx.x * 128;
    const int z  = blockIdx.z;
    Ah  += (long)z * aBatch;  Al  += (long)z * aBatch;
    A2h += (long)z * aBatch;  A2l += (long)z * aBatch;
    Bh  += (long)z * bBatch;  Bl  += (long)z * bBatch;

    const int nchunks = K / KC;

    // ---- cp.async loader for chunk c into stage s (2048 x 16B, 16/thread) ----
    auto issue = [&](int c, int s) {
        if (c >= nchunks) return;
        const int k0 = c * KC;
        const __nv_bfloat16* pAh = Ah;
        const __nv_bfloat16* pAl = Al;
        int ak = k0, la = lda;
        if (k0 >= kSplit) { pAh = A2h; pAl = A2l; ak = k0 - kSplit; la = lda2; }
        const uint32_t st = sb + s * STG;
#pragma unroll
        for (int j = 0; j < 16; j++) {
            int idx = tid + j * 128;          // 0..2047
            int mat  = idx >> 9;              // 0=Ahi 1=Alo 2=Bhi 3=Blo
            int i2   = idx & 511;
            int row  = i2 >> 2;
            int part = i2 & 3;
            uint32_t dst = st + (uint32_t)mat * AMATB + (uint32_t)row * ROWB +
                           (uint32_t)((part ^ (row & 3)) << 4);
            const __nv_bfloat16* src;
            if (mat == 0)      src = pAh + (long)(m0 + row) * la  + ak + part * 8;
            else if (mat == 1) src = pAl + (long)(m0 + row) * la  + ak + part * 8;
            else if (mat == 2) src = Bh  + (long)(n0 + row) * ldb + k0 + part * 8;
            else               src = Bl  + (long)(n0 + row) * ldb + k0 + part * 8;
            CP_ASYNC16(dst, src);
        }
    };

    float acc[4][8][4];
#pragma unroll
    for (int mf = 0; mf < 4; mf++)
#pragma unroll
        for (int nf = 0; nf < 8; nf++)
#pragma unroll
            for (int r = 0; r < 4; r++) acc[mf][nf][r] = 0.f;

    issue(0, 0); CP_COMMIT();
    issue(1, 1); CP_COMMIT();

    const int rowA   = l & 15;
    const int partA0 = l >> 4;
    const int rowBl  = ((l >> 4) << 3) + (l & 7);
    const int partB0 = (l >> 3) & 1;

    for (int c = 0; c < nchunks; c++) {
        CP_WAIT1();                      // my warp's chunk-c group landed
        __syncthreads();                 // ALL warps landed (visibility) + done reading old stage
        issue(c + 2, (c + 2) % NSTG);    // refill stage consumed at chunk c-1
        CP_COMMIT();

        const uint32_t base = sb + (c % NSTG) * STG;
#pragma unroll
        for (int ks = 0; ks < 2; ks++) {
            uint32_t a_hi[4][4], a_lo[4][4];
#pragma unroll
            for (int mf = 0; mf < 4; mf++) {
                const int row  = wm * 64 + mf * 16 + rowA;
                const int prt  = ks * 2 + partA0;
                uint32_t off = base + (uint32_t)row * ROWB +
                               (uint32_t)((prt ^ (row & 3)) << 4);
                LDM4(a_hi[mf], off);
                LDM4(a_lo[mf], off + AMATB);
            }
            uint32_t b_hi[4][4], b_lo[4][4];
#pragma unroll
            for (int nf2 = 0; nf2 < 4; nf2++) {
                const int row  = wn * 64 + nf2 * 16 + rowBl;
                const int prt  = ks * 2 + partB0;
                uint32_t off = base + 2 * AMATB + (uint32_t)row * ROWB +
                               (uint32_t)((prt ^ (row & 3)) << 4);
                LDM4(b_hi[nf2], off);
                LDM4(b_lo[nf2], off + BMATB);
            }
#pragma unroll
            for (int mf = 0; mf < 4; mf++)
#pragma unroll
                for (int nf2 = 0; nf2 < 4; nf2++)
#pragma unroll
                    for (int h = 0; h < 2; h++) {
                        const int nf = nf2 * 2 + h;
                        MMA_BF16(acc[mf][nf], a_hi[mf], b_hi[nf2][h * 2], b_hi[nf2][h * 2 + 1]);
                        MMA_BF16(acc[mf][nf], a_hi[mf], b_lo[nf2][h * 2], b_lo[nf2][h * 2 + 1]);
                        MMA_BF16(acc[mf][nf], a_lo[mf], b_hi[nf2][h * 2], b_hi[nf2][h * 2 + 1]);
                    }
        }
    }

    float* Cb = C + (long)z * cBatch;
    __nv_bfloat16* Chb = Chi + (long)z * cBatch;
    __nv_bfloat16* Clb = Clo + (long)z * cBatch;
#pragma unroll
    for (int mf = 0; mf < 4; mf++)
#pragma unroll
        for (int nf = 0; nf < 8; nf++)
#pragma unroll
            for (int h2 = 0; h2 < 2; h2++) {
                const int m = m0 + wm * 64 + mf * 16 + h2 * 8 + (l >> 2);
                const int n = n0 + wn * 64 + nf * 8 + (l & 3) * 2;
                float v0 = acc[mf][nf][h2 * 2 + 0];
                float v1 = acc[mf][nf][h2 * 2 + 1];
                if (EPI == 0) {
                    float2 t = make_float2(v0, v1);
                    *(float2*)&Cb[(long)m * ldc + n] = t;
                } else if (EPI == 2) {
                    float2 t;
                    t.x = tanhf(v0 + bias[n]);
                    t.y = tanhf(v1 + bias[n + 1]);
                    *(float2*)&Cb[(long)m * ldc + n] = t;
                } else {
                    __nv_bfloat16 h0 = __float2bfloat16(v0);
                    __nv_bfloat16 h1 = __float2bfloat16(v1);
                    __nv_bfloat16 l0 = __float2bfloat16(v0 - __bfloat162float(h0));
                    __nv_bfloat16 l1 = __float2bfloat16(v1 - __bfloat162float(h1));
                    __nv_bfloat162 hp; hp.x = h0; hp.y = h1;
                    __nv_bfloat162 lp; lp.x = l0; lp.y = l1;
                    *(__nv_bfloat162*)&Chb[(long)m * ldc + n] = hp;
                    *(__nv_bfloat162*)&Clb[(long)m * ldc + n] = lp;
                }
            }
}

// ---------------------------------------------------------------------------
// fp32 -> bf16 hi/lo split (elementwise, coalesced float4 per thread)
// ---------------------------------------------------------------------------
__global__ __launch_bounds__(256)
void cvt_hilo(const float* __restrict__ x, __nv_bfloat16* __restrict__ hi,
              __nv_bfloat16* __restrict__ lo, long n4)
{
    long i = (long)blockIdx.x * blockDim.x + threadIdx.x;
    if (i >= n4) return;
    float4 v = ((const float4*)x)[i];
    float f[4] = {v.x, v.y, v.z, v.w};
    __nv_bfloat16 h[4], l[4];
#pragma unroll
    for (int j = 0; j < 4; j++) {
        h[j] = __float2bfloat16(f[j]);
        l[j] = __float2bfloat16(f[j] - __bfloat162float(h[j]));
    }
    *(uint2*)&hi[i * 4] = *(uint2*)h;
    *(uint2*)&lo[i * 4] = *(uint2*)l;
}

// ---------------------------------------------------------------------------
// ctx [B,S,H] fp32 -> ctx hi/lo [B,S,H] + ctxT hi/lo [B,H,S]  (one read)
// ---------------------------------------------------------------------------
__global__ __launch_bounds__(256)
void transpose_cvt(const float* __restrict__ ctx,
                   __nv_bfloat16* __restrict__ chi, __nv_bfloat16* __restrict__ clo,
                   __nv_bfloat16* __restrict__ thi, __nv_bfloat16* __restrict__ tlo)
{
    __shared__ float tile[32][33];
    const int h0 = blockIdx.x * 32;
    const int s0 = blockIdx.y * 32;
    const int z  = blockIdx.z;
    const int tx = threadIdx.x & 31;
    const int ty = threadIdx.x >> 5;
    const long ibase = (long)z * Ss * Hh;
    const long obase = (long)z * Hh * Ss;
#pragma unroll
    for (int i = 0; i < 4; i++) {
        int s = s0 + ty + i * 8;
        float v = ctx[ibase + (long)s * Hh + h0 + tx];
        tile[ty + i * 8][tx] = v;
        __nv_bfloat16 hb = __float2bfloat16(v);
        __nv_bfloat16 lb = __float2bfloat16(v - __bfloat162float(hb));
        long o = ibase + (long)s * Hh + h0 + tx;
        chi[o] = hb;
        clo[o] = lb;
    }
    __syncthreads();
#pragma unroll
    for (int i = 0; i < 4; i++) {
        int h = h0 + ty + i * 8;
        float v = tile[tx][ty + i * 8];
        __nv_bfloat16 hb = __float2bfloat16(v);
        __nv_bfloat16 lb = __float2bfloat16(v - __bfloat162float(hb));
        long o = obase + (long)h * Ss + s0 + tx;
        thi[o] = hb;
        tlo[o] = lb;
    }
}

// ---------------------------------------------------------------------------
// In-place row softmax over S=2048 (coalesced tid+i*256), warp-shuffle
// reductions (2 syncs per reduction instead of 8), emits bf16 hi/lo.
// ---------------------------------------------------------------------------
__global__ __launch_bounds__(256)
void softmax_kernel(float* __restrict__ attn, __nv_bfloat16* __restrict__ ahi,
                    __nv_bfloat16* __restrict__ alo)
{
    __shared__ float red[8];
    const long row = blockIdx.x;
    float* p = attn + row * (long)Ss;
    const int tid = threadIdx.x;
    const int lane = tid & 31;
    const int warp = tid >> 5;

    float v[8];
    float mx = -INFINITY;
#pragma unroll
    for (int i = 0; i < 8; i++) {
        v[i] = p[tid + i * 256];
        mx = fmaxf(mx, v[i]);
    }
#pragma unroll
    for (int off = 16; off > 0; off >>= 1)
        mx = fmaxf(mx, __shfl_xor_sync(0xFFFFFFFF, mx, off));
    if (lane == 0) red[warp] = mx;
    __syncthreads();
    {
        float t = red[lane & 7];
#pragma unroll
        for (int off = 4; off > 0; off >>= 1)
            t = fmaxf(t, __shfl_xor_sync(0xFFFFFFFF, t, off));
        mx = t;   // all lanes of every warp now hold block max (broadcast via red)
    }

    float sum = 0.f;
#pragma unroll
    for (int i = 0; i < 8; i++) {
        v[i] = __expf(v[i] - mx);
        sum += v[i];
    }
#pragma unroll
    for (int off = 16; off > 0; off >>= 1)
        sum += __shfl_xor_sync(0xFFFFFFFF, sum, off);
    __syncthreads();           // red[] reuse guard
    if (lane == 0) red[warp] = sum;
    __syncthreads();
    {
        float t = red[lane & 7];
#pragma unroll
        for (int off = 4; off > 0; off >>= 1)
            t += __shfl_xor_sync(0xFFFFFFFF, t, off);
        sum = t;
    }
    const float inv = 1.f / sum;

#pragma unroll
    for (int i = 0; i < 8; i++) {
        float w = v[i] * inv;
        long idx = row * (long)Ss + tid + i * 256;
        p[tid + i * 256] = w;
        __nv_bfloat16 hb = __float2bfloat16(w);
        ahi[idx] = hb;
        alo[idx] = __float2bfloat16(w - __bfloat162float(hb));
    }
}

// ---------------------------------------------------------------------------
extern "C" void kernel_launch(void* const* d_in, const int* in_sizes, int n_in,
                              void* d_out, int out_size)
{
    const float* output  = (const float*)d_in[0];
    const float* context = (const float*)d_in[1];
    const float* attn_w  = (const float*)d_in[2];
    const float* w2      = (const float*)d_in[3];
    const float* b2      = (const float*)d_in[4];

    float* out  = (float*)d_out;                   // [B,T,H]
    float* attn = out + (long)MT * Hh;             // [B,T,S]

    void *outhi, *outlo, *whi, *wlo, *w2hi, *w2lo, *ctxhi, *ctxlo;
    void *ctxthi, *ctxtlo, *qhi, *qlo, *athi, *atlo, *mixhi, *mixlo;
    cudaGetSymbolAddress(&outhi, g_out_hi);   cudaGetSymbolAddress(&outlo, g_out_lo);
    cudaGetSymbolAddress(&whi, g_w_hi);       cudaGetSymbolAddress(&wlo, g_w_lo);
    cudaGetSymbolAddress(&w2hi, g_w2_hi);     cudaGetSymbolAddress(&w2lo, g_w2_lo);
    cudaGetSymbolAddress(&ctxhi, g_ctx_hi);   cudaGetSymbolAddress(&ctxlo, g_ctx_lo);
    cudaGetSymbolAddress(&ctxthi, g_ctxT_hi); cudaGetSymbolAddress(&ctxtlo, g_ctxT_lo);
    cudaGetSymbolAddress(&qhi, g_q_hi);       cudaGetSymbolAddress(&qlo, g_q_lo);
    cudaGetSymbolAddress(&athi, g_attn_hi);   cudaGetSymbolAddress(&atlo, g_attn_lo);
    cudaGetSymbolAddress(&mixhi, g_mix_hi);   cudaGetSymbolAddress(&mixlo, g_mix_lo);

    cudaFuncSetAttribute(hmma_gemm<0>, cudaFuncAttributeMaxDynamicSharedMemorySize, SMEM_TOTAL);
    cudaFuncSetAttribute(hmma_gemm<1>, cudaFuncAttributeMaxDynamicSharedMemorySize, SMEM_TOTAL);
    cudaFuncSetAttribute(hmma_gemm<2>, cudaFuncAttributeMaxDynamicSharedMemorySize, SMEM_TOTAL);

    const __nv_bfloat16* OH = (const __nv_bfloat16*)outhi;
    const __nv_bfloat16* OL = (const __nv_bfloat16*)outlo;
    const __nv_bfloat16* WH = (const __nv_bfloat16*)whi;
    const __nv_bfloat16* WL = (const __nv_bfloat16*)wlo;
    const __nv_bfloat16* W2H = (const __nv_bfloat16*)w2hi;
    const __nv_bfloat16* W2L = (const __nv_bfloat16*)w2lo;
    const __nv_bfloat16* CH = (const __nv_bfloat16*)ctxhi;
    const __nv_bfloat16* CL = (const __nv_bfloat16*)ctxlo;
    const __nv_bfloat16* CTH = (const __nv_bfloat16*)ctxthi;
    const __nv_bfloat16* CTL = (const __nv_bfloat16*)ctxtlo;
    const __nv_bfloat16* QH = (const __nv_bfloat16*)qhi;
    const __nv_bfloat16* QL = (const __nv_bfloat16*)qlo;
    const __nv_bfloat16* AH = (const __nv_bfloat16*)athi;
    const __nv_bfloat16* AL = (const __nv_bfloat16*)atlo;
    const __nv_bfloat16* MH = (const __nv_bfloat16*)mixhi;
    const __nv_bfloat16* ML = (const __nv_bfloat16*)mixlo;

    // fork-join resources (host-side only; no device memory)
    cudaStream_t side;
    cudaStreamCreateWithFlags(&side, cudaStreamNonBlocking);
    cudaEvent_t ev0, ev1, evA, evB;
    cudaEventCreateWithFlags(&ev0, cudaEventDisableTiming);
    cudaEventCreateWithFlags(&ev1, cudaEventDisableTiming);
    cudaEventCreateWithFlags(&evA, cudaEventDisableTiming);
    cudaEventCreateWithFlags(&evB, cudaEventDisableTiming);

    // ---- fork: side does ctx transpose+convert and w2 convert ----
    cudaEventRecord(ev0, 0);
    cudaStreamWaitEvent(side, ev0, 0);
    {
        dim3 g(Hh / 32, Ss / 32, Bb);
        transpose_cvt<<<g, 256, 0, side>>>(context, (__nv_bfloat16*)ctxhi, (__nv_bfloat16*)ctxlo,
                                           (__nv_bfloat16*)ctxthi, (__nv_bfloat16*)ctxtlo);
    }
    cvt_hilo<<<((long)Hh * 2 * Hh / 4 + 255) / 256, 256, 0, side>>>(
        w2, (__nv_bfloat16*)w2hi, (__nv_bfloat16*)w2lo, (long)Hh * 2 * Hh / 4);
    cudaEventRecord(ev1, side);

    // ---- main: out/w converts + GEMM1 ----
    cvt_hilo<<<(MT * (long)Hh / 4 + 255) / 256, 256>>>(output, (__nv_bfloat16*)outhi, (__nv_bfloat16*)outlo, MT * (long)Hh / 4);
    cvt_hilo<<<((long)Hh * Hh / 4 + 255) / 256, 256>>>(attn_w, (__nv_bfloat16*)whi, (__nv_bfloat16*)wlo, (long)Hh * Hh / 4);
    {
        dim3 grid(Hh / 128, MT / 128, 1);
        hmma_gemm<1><<<grid, 128, SMEM_TOTAL>>>(OH, OL, OH, OL, 1 << 30, Hh, Hh, 0L,
                                                WH, WL, Hh, 0L, Hh,
                                                nullptr, (long)MT * Hh, Hh,
                                                (__nv_bfloat16*)qhi, (__nv_bfloat16*)qlo, nullptr);
    }
    cudaStreamWaitEvent(0, ev1, 0);   // join: ctx ready

    // ---- GEMM2 in two batch halves ----
    const long aB2 = (long)Tt * Hh, bB2 = (long)Ss * Hh, cB2 = (long)Tt * Ss;
    {
        dim3 grid(Ss / 128, Tt / 128, HB);
        hmma_gemm<0><<<grid, 128, SMEM_TOTAL>>>(QH, QL, QH, QL, 1 << 30, Hh, Hh, aB2,
                                                CH, CL, Hh, bB2, Hh,
                                                attn, cB2, Ss, nullptr, nullptr, nullptr);
    }
    cudaEventRecord(evA, 0);
    {
        dim3 grid(Ss / 128, Tt / 128, HB);
        hmma_gemm<0><<<grid, 128, SMEM_TOTAL>>>(QH + HB * aB2, QL + HB * aB2,
                                                QH + HB * aB2, QL + HB * aB2, 1 << 30, Hh, Hh, aB2,
                                                CH + HB * bB2, CL + HB * bB2, Hh, bB2, Hh,
                                                attn + HB * cB2, cB2, Ss, nullptr, nullptr, nullptr);
    }

    // ---- side: softmax h1 + GEMM3 h1 ----
    const long aB3 = (long)Tt * Ss, bB3 = (long)Hh * Ss, cB3 = (long)Tt * Hh;
    cudaStreamWaitEvent(side, evA, 0);
    softmax_kernel<<<MT / 2, 256, 0, side>>>(attn, (__nv_bfloat16*)athi, (__nv_bfloat16*)atlo);
    {
        dim3 grid(Hh / 128, Tt / 128, HB);
        hmma_gemm<1><<<grid, 128, SMEM_TOTAL, side>>>(AH, AL, AH, AL, 1 << 30, Ss, Ss, aB3,
                                                      CTH, CTL, Ss, bB3, Ss,
                                                      nullptr, cB3, Hh,
                                                      (__nv_bfloat16*)mixhi, (__nv_bfloat16*)mixlo, nullptr);
    }
    cudaEventRecord(evB, side);

    // ---- main: softmax h2 + GEMM3 h2 ----
    softmax_kernel<<<MT / 2, 256>>>(attn + HB * cB2,
                                    (__nv_bfloat16*)athi + HB * cB2,
                                    (__nv_bfloat16*)atlo + HB * cB2);
    {
        dim3 grid(Hh / 128, Tt / 128, HB);
        hmma_gemm<1><<<grid, 128, SMEM_TOTAL>>>(AH + HB * aB3, AL + HB * aB3,
                                                AH + HB * aB3, AL + HB * aB3, 1 << 30, Ss, Ss, aB3,
                                                CTH + HB * bB3, CTL + HB * bB3, Ss, bB3, Ss,
                                                nullptr, cB3, Hh,
                                                (__nv_bfloat16*)mixhi + HB * cB3,
                                                (__nv_bfloat16*)mixlo + HB * cB3, nullptr);
    }
    cudaStreamWaitEvent(0, evB, 0);   // join: mix h1 ready

    // ---- GEMM4 ----
    {
        dim3 grid(Hh / 128, MT / 128, 1);
        hmma_gemm<2><<<grid, 128, SMEM_TOTAL>>>(MH, ML, QH, QL, Hh, Hh, Hh, 0L,
                                                W2H, W2L, 2 * Hh, 0L, 2 * Hh,
                                                out, (long)MT * Hh, Hh,
                                                nullptr, nullptr, b2);
    }
    // note: streams/events intentionally not destroyed while referenced by capture
}